// round 3
// baseline (speedup 1.0000x reference)
#include <cuda_runtime.h>
#include <math.h>

// Moebius transform on 3-D blocks + log|det J| row reduction.
// One CTA per batch row; thread t handles floats [t*12, t*12+12) = 4 blocks.
// All global traffic is float4 (128B-per-warp coalesced).

__device__ __forceinline__ float moebius_block3(
    float a0, float a1, float a2,     // x block
    float v0, float v1, float v2,     // w block
    float& y0, float& y1, float& y2)  // y block out
{
    // radial normalization
    float xns   = fmaf(a0, a0, fmaf(a1, a1, a2 * a2));
    float inv   = rsqrtf(xns);
    float xnorm = xns * inv;                 // sqrt(xns)

    float n0 = a0 * inv, n1 = a1 * inv, n2 = a2 * inv;
    float p0 = n0 + v0,  p1 = n1 + v1,  p2 = n2 + v2;   // xn + w

    float wns  = fmaf(v0, v0, fmaf(v1, v1, v2 * v2));
    float pns  = fmaf(p0, p0, fmaf(p1, p1, p2 * p2));
    float invp = __frcp_rn(pns);
    float c    = (1.0f - wns) * invp;

    float yn0 = fmaf(c, p0, v0);
    float yn1 = fmaf(c, p1, v1);
    float yn2 = fmaf(c, p2, v2);

    y0 = xnorm * yn0;
    y1 = xnorm * yn1;
    y2 = xnorm * yn2;

    // Jacobian: dxn_dx = inv * (I - n n^T)
    // g = dxn_dx @ p = inv * (p - n * (n.p))
    float np = fmaf(n0, p0, fmaf(n1, p1, n2 * p2));
    float g0 = inv * (p0 - n0 * np);
    float g1 = inv * (p1 - n1 * np);
    float g2 = inv * (p2 - n2 * np);

    float s  = xnorm * c;          // xnorm * (1-wns)/pns
    float t2 = 2.0f * invp;

    // J_ij = s * ( inv*(delta_ij - n_i n_j) - t2 * p_i * g_j ) + yn_i * n_j
    float si = s * inv;
    float J00 = si * (1.0f - n0 * n0) - s * t2 * p0 * g0 + yn0 * n0;
    float J01 = si * (      - n0 * n1) - s * t2 * p0 * g1 + yn0 * n1;
    float J02 = si * (      - n0 * n2) - s * t2 * p0 * g2 + yn0 * n2;
    float J10 = si * (      - n1 * n0) - s * t2 * p1 * g0 + yn1 * n0;
    float J11 = si * (1.0f - n1 * n1) - s * t2 * p1 * g1 + yn1 * n1;
    float J12 = si * (      - n1 * n2) - s * t2 * p1 * g2 + yn1 * n2;
    float J20 = si * (      - n2 * n0) - s * t2 * p2 * g0 + yn2 * n0;
    float J21 = si * (      - n2 * n1) - s * t2 * p2 * g1 + yn2 * n1;
    float J22 = si * (1.0f - n2 * n2) - s * t2 * p2 * g2 + yn2 * n2;

    float det = J00 * (J11 * J22 - J12 * J21)
              - J01 * (J10 * J22 - J12 * J20)
              + J02 * (J10 * J21 - J11 * J20);

    return logf(fabsf(det));
}

__global__ void __launch_bounds__(256)
moebius_kernel(const float* __restrict__ x,
               const float* __restrict__ w,
               float* __restrict__ y,
               float* __restrict__ logdet,
               int F)
{
    const int row = blockIdx.x;
    const int t   = threadIdx.x;
    const int base = row * F + t * 12;           // B*F < 2^31, fits int

    // 3x float4 loads of x and w each (12 floats = 4 blocks of 3)
    const float4* xv = reinterpret_cast<const float4*>(x + base);
    const float4* wv = reinterpret_cast<const float4*>(w + base);
    float4 xa = xv[0], xb = xv[1], xc = xv[2];
    float4 wa = wv[0], wb = wv[1], wc = wv[2];

    float xs[12] = {xa.x, xa.y, xa.z, xa.w, xb.x, xb.y, xb.z, xb.w,
                    xc.x, xc.y, xc.z, xc.w};
    float ws[12] = {wa.x, wa.y, wa.z, wa.w, wb.x, wb.y, wb.z, wb.w,
                    wc.x, wc.y, wc.z, wc.w};
    float ys[12];

    float acc = 0.0f;
#pragma unroll
    for (int k = 0; k < 4; k++) {
        acc += moebius_block3(xs[3*k], xs[3*k+1], xs[3*k+2],
                              ws[3*k], ws[3*k+1], ws[3*k+2],
                              ys[3*k], ys[3*k+1], ys[3*k+2]);
    }

    float4* yv = reinterpret_cast<float4*>(y + base);
    yv[0] = make_float4(ys[0], ys[1], ys[2],  ys[3]);
    yv[1] = make_float4(ys[4], ys[5], ys[6],  ys[7]);
    yv[2] = make_float4(ys[8], ys[9], ys[10], ys[11]);

    // Reduce acc over the CTA (one row) — warp shuffle then shared.
#pragma unroll
    for (int o = 16; o > 0; o >>= 1)
        acc += __shfl_xor_sync(0xffffffffu, acc, o);

    __shared__ float ssum[32];
    const int lane = t & 31;
    const int warp = t >> 5;
    if (lane == 0) ssum[warp] = acc;
    __syncthreads();

    if (t == 0) {
        const int nwarps = blockDim.x >> 5;
        float s = 0.0f;
        for (int i = 0; i < nwarps; i++) s += ssum[i];
        logdet[row] = s;
    }
}

extern "C" void kernel_launch(void* const* d_in, const int* in_sizes, int n_in,
                              void* d_out, int out_size)
{
    const float* x = (const float*)d_in[0];
    const float* w = (const float*)d_in[1];
    float* out = (float*)d_out;

    const int total = in_sizes[0];          // B * F
    const int batch = out_size - total;     // out = y (B*F) ++ logdet (B)
    const int F     = total / batch;        // 3072

    float* y      = out;
    float* logdet = out + (size_t)total;

    const int threads = F / 12;             // 256: 4 blocks of 3 per thread
    moebius_kernel<<<batch, threads>>>(x, w, y, logdet, F);
}

// round 4
// speedup vs baseline: 1.0437x; 1.0437x over previous
#include <cuda_runtime.h>
#include <math.h>

// Moebius transform on 3-D blocks + log|det J| row reduction.
// One CTA per batch row; thread t handles floats [t*12, t*12+12) = 4 blocks.
// Determinant via conformal-map closed form: |det J| = c^2 * |yn . Hn|,
// c = (1-|w|^2)/|n+w|^2, Hn = n - 2 p (n.p)/|p|^2 (Householder image of n).

__device__ __forceinline__ float moebius_block3(
    float a0, float a1, float a2,     // x block
    float v0, float v1, float v2,     // w block
    float& y0, float& y1, float& y2)  // y block out
{
    // radial normalization
    float xns   = fmaf(a0, a0, fmaf(a1, a1, a2 * a2));
    float inv   = rsqrtf(xns);
    float xnorm = xns * inv;                 // sqrt(xns)

    float n0 = a0 * inv, n1 = a1 * inv, n2 = a2 * inv;
    float p0 = n0 + v0,  p1 = n1 + v1,  p2 = n2 + v2;   // n + w

    float wns  = fmaf(v0, v0, fmaf(v1, v1, v2 * v2));
    float pns  = fmaf(p0, p0, fmaf(p1, p1, p2 * p2));
    float invp = __frcp_rn(pns);
    float c    = (1.0f - wns) * invp;

    float yn0 = fmaf(c, p0, v0);
    float yn1 = fmaf(c, p1, v1);
    float yn2 = fmaf(c, p2, v2);

    y0 = xnorm * yn0;
    y1 = xnorm * yn1;
    y2 = xnorm * yn2;

    // |det J| = c^2 * | yn . (n - 2 p (n.p)/|p|^2) |
    float np = fmaf(n0, p0, fmaf(n1, p1, n2 * p2));
    float t  = 2.0f * np * invp;
    float h0 = fmaf(-t, p0, n0);
    float h1 = fmaf(-t, p1, n1);
    float h2 = fmaf(-t, p2, n2);
    float d  = fmaf(yn0, h0, fmaf(yn1, h1, yn2 * h2));

    return c * c * fabsf(d);
}

__global__ void __launch_bounds__(256)
moebius_kernel(const float* __restrict__ x,
               const float* __restrict__ w,
               float* __restrict__ y,
               float* __restrict__ logdet,
               int F)
{
    const int row  = blockIdx.x;
    const int t    = threadIdx.x;
    const int base = row * F + t * 12;           // B*F < 2^31, fits int

    // 3x float4 streaming loads of x and w each (12 floats = 4 blocks of 3)
    const float4* xv = reinterpret_cast<const float4*>(x + base);
    const float4* wv = reinterpret_cast<const float4*>(w + base);
    float4 xa = __ldcs(xv + 0), xb = __ldcs(xv + 1), xc = __ldcs(xv + 2);
    float4 wa = __ldcs(wv + 0), wb = __ldcs(wv + 1), wc = __ldcs(wv + 2);

    float xs[12] = {xa.x, xa.y, xa.z, xa.w, xb.x, xb.y, xb.z, xb.w,
                    xc.x, xc.y, xc.z, xc.w};
    float ws[12] = {wa.x, wa.y, wa.z, wa.w, wb.x, wb.y, wb.z, wb.w,
                    wc.x, wc.y, wc.z, wc.w};
    float ys[12];

    float prod = 1.0f;
#pragma unroll
    for (int k = 0; k < 4; k++) {
        prod *= moebius_block3(xs[3*k], xs[3*k+1], xs[3*k+2],
                               ws[3*k], ws[3*k+1], ws[3*k+2],
                               ys[3*k], ys[3*k+1], ys[3*k+2]);
    }

    float4* yv = reinterpret_cast<float4*>(y + base);
    __stcs(yv + 0, make_float4(ys[0], ys[1], ys[2],  ys[3]));
    __stcs(yv + 1, make_float4(ys[4], ys[5], ys[6],  ys[7]));
    __stcs(yv + 2, make_float4(ys[8], ys[9], ys[10], ys[11]));

    // log of product of the 4 |det|s: one fast log per thread
    float acc = __logf(prod);

    // Reduce acc over the CTA (one row) — warp shuffle then shared.
#pragma unroll
    for (int o = 16; o > 0; o >>= 1)
        acc += __shfl_xor_sync(0xffffffffu, acc, o);

    __shared__ float ssum[8];
    const int lane = t & 31;
    const int warp = t >> 5;
    if (lane == 0) ssum[warp] = acc;
    __syncthreads();

    if (warp == 0) {
        float s = (lane < 8) ? ssum[lane] : 0.0f;
#pragma unroll
        for (int o = 4; o > 0; o >>= 1)
            s += __shfl_xor_sync(0xffffffffu, s, o);
        if (lane == 0) logdet[row] = s;
    }
}

extern "C" void kernel_launch(void* const* d_in, const int* in_sizes, int n_in,
                              void* d_out, int out_size)
{
    const float* x = (const float*)d_in[0];
    const float* w = (const float*)d_in[1];
    float* out = (float*)d_out;

    const int total = in_sizes[0];          // B * F
    const int batch = out_size - total;     // out = y (B*F) ++ logdet (B)
    const int F     = total / batch;        // 3072

    float* y      = out;
    float* logdet = out + (size_t)total;

    const int threads = F / 12;             // 256: 4 blocks of 3 per thread
    moebius_kernel<<<batch, threads>>>(x, w, y, logdet, F);
}